// round 6
// baseline (speedup 1.0000x reference)
#include <cuda_runtime.h>
#include <cuda_fp16.h>
#include <math.h>
#include <cstdint>

#define BB   2
#define LL   4096
#define DD   1024
#define NH   16
#define HDIM 64
#define BSZ  256
#define NBLK (LL / BSZ)     // 16
#define MR   (BB * LL)      // 8192

// Scratch (allocation-free, __device__ globals)
__device__ float  g_Q[BB * NH * LL * HDIM];
__device__ float  g_K[BB * NH * LL * HDIM];
__device__ float  g_V[BB * NH * LL * HDIM];
__device__ __half g_Oh[MR * DD];
// fp16 operands
__device__ __half g_Xh[MR * DD];
__device__ __half g_Wqkvh[3 * DD * DD];
__device__ __half g_Wouth[DD * DD];

// ---------------------------------------------------------------------------
// helpers
// ---------------------------------------------------------------------------
__device__ __forceinline__ uint32_t smem_u32(const void* p) {
    uint32_t a;
    asm("{ .reg .u64 t; cvta.to.shared.u64 t, %1; cvt.u32.u64 %0, t; }" : "=r"(a) : "l"(p));
    return a;
}
__device__ __forceinline__ void cp16(void* smem_dst, const void* gmem_src) {
    unsigned s = (unsigned)__cvta_generic_to_shared(smem_dst);
    asm volatile("cp.async.cg.shared.global [%0], [%1], 16;\n" :: "r"(s), "l"(gmem_src));
}
__device__ __forceinline__ void cp_commit() { asm volatile("cp.async.commit_group;\n"); }
template <int N>
__device__ __forceinline__ void cp_wait() { asm volatile("cp.async.wait_group %0;\n" :: "n"(N)); }

__device__ __forceinline__ void ldsm4(unsigned* r, uint32_t addr) {
    asm volatile("ldmatrix.sync.aligned.m8n8.x4.shared.b16 {%0,%1,%2,%3}, [%4];"
                 : "=r"(r[0]), "=r"(r[1]), "=r"(r[2]), "=r"(r[3]) : "r"(addr));
}
__device__ __forceinline__ void mma_f16(float* d, const unsigned* a, const unsigned* b) {
    asm volatile(
        "mma.sync.aligned.m16n8k16.row.col.f32.f16.f16.f32 "
        "{%0,%1,%2,%3}, {%4,%5,%6,%7}, {%8,%9}, {%0,%1,%2,%3};\n"
        : "+f"(d[0]), "+f"(d[1]), "+f"(d[2]), "+f"(d[3])
        : "r"(a[0]), "r"(a[1]), "r"(a[2]), "r"(a[3]),
          "r"(b[0]), "r"(b[1]));
}

// ---------------------------------------------------------------------------
// Pre-pass: fp32 -> fp16
// ---------------------------------------------------------------------------
__global__ void f2h_kernel(const float4* __restrict__ src, uint2* __restrict__ dst, int n4)
{
    int i = blockIdx.x * blockDim.x + threadIdx.x;
    if (i < n4) {
        float4 v = src[i];
        __half2 h0 = __floats2half2_rn(v.x, v.y);
        __half2 h1 = __floats2half2_rn(v.z, v.w);
        dst[i] = make_uint2(*(unsigned*)&h0, *(unsigned*)&h1);
    }
}

// ---------------------------------------------------------------------------
// fp16 tensor-core GEMM: C[M,N] = A[M,K] * B[N,K]^T  (fp32 accumulate)
// CTA 128x128, BK=32, 256 threads = 8 warps (2x4), warp tile 64x32.
// m16n8k16 mma, ldmatrix.x4 fragments, smem rows stride 40 halves
// (conflict-free ldmatrix), 3-stage cp.async pipeline. 2 CTAs/SM.
// MODE 0: scatter fp32 epilogue into g_Q/g_K/g_V; MODE 1: fp32 row-major C.
// ---------------------------------------------------------------------------
#define ROWH   40
#define TILE_H (128 * ROWH)           // halves per operand tile (5120)
#define STAGE_H (2 * TILE_H)          // halves per stage (10240 = 20480 B)
#define NSTAGE 3
#define GEMM_SMEM (NSTAGE * STAGE_H * 2)   // 61440 B

template <int MODE>
__global__ __launch_bounds__(256, 2)
void mm_f16(const __half* __restrict__ A, const __half* __restrict__ Bm,
            float* __restrict__ C, int Kdim, int Ndim)
{
    extern __shared__ __half smh[];
    const uint32_t smem_base = smem_u32(smh);

    const int m0 = blockIdx.y * 128;
    const int n0 = blockIdx.x * 128;
    const int t  = threadIdx.x;
    const int warp = t >> 5, lane = t & 31;
    const int wm = (warp >> 2) * 64;   // {0, 64}
    const int wn = (warp & 3) * 32;    // {0, 32, 64, 96}
    const int g = lane >> 2;           // 0..7
    const int q = lane & 3;            // 0..3

    float acc[4][4][4];
#pragma unroll
    for (int i = 0; i < 4; i++)
#pragma unroll
        for (int j = 0; j < 4; j++)
#pragma unroll
            for (int r = 0; r < 4; r++) acc[i][j][r] = 0.f;

    // ldmatrix lane addressing (byte offsets within a tile)
    // A: row = wm + mi*16 + (lane&15), col = ks*16 + (lane>>4)*8
    const uint32_t a_off = (uint32_t)((wm + (lane & 15)) * ROWH + (lane >> 4) * 8) * 2;
    // B: row = wn + np*16 + (lane&7) + ((lane>>4)<<3), col = ks*16 + ((lane>>3)&1)*8
    const uint32_t b_off = (uint32_t)((wn + (lane & 7) + ((lane >> 4) << 3)) * ROWH
                                      + ((lane >> 3) & 1) * 8) * 2;

    const int KT = Kdim >> 5;

    auto prefetch = [&](int kt, int s) {
        __half* As = smh + s * STAGE_H;
        __half* Bs = As + TILE_H;
        const int k0 = kt << 5;
#pragma unroll
        for (int u = 0; u < 2; u++) {            // A: 512 16B chunks
            int idx = t + u * 256;
            int row = idx >> 2, c8 = (idx & 3) << 3;
            cp16(As + row * ROWH + c8, A + (size_t)(m0 + row) * Kdim + k0 + c8);
        }
#pragma unroll
        for (int u = 0; u < 2; u++) {            // B: 512 16B chunks
            int idx = t + u * 256;
            int row = idx >> 2, c8 = (idx & 3) << 3;
            cp16(Bs + row * ROWH + c8, Bm + (size_t)(n0 + row) * Kdim + k0 + c8);
        }
    };

    prefetch(0, 0); cp_commit();
    prefetch(1, 1); cp_commit();

    int sbuf = 0;
    for (int kt = 0; kt < KT; kt++) {
        if (kt + 1 < KT) cp_wait<1>(); else cp_wait<0>();
        __syncthreads();

        if (kt + 2 < KT) {
            int s2 = sbuf + 2; if (s2 >= NSTAGE) s2 -= NSTAGE;
            prefetch(kt + 2, s2);
            cp_commit();
        }

        const uint32_t As_u = smem_base + (uint32_t)(sbuf * STAGE_H) * 2;
        const uint32_t Bs_u = As_u + TILE_H * 2;

#pragma unroll
        for (int ks = 0; ks < 2; ks++) {
            unsigned af[4][4], bf[2][4];
            const uint32_t kboff = (uint32_t)(ks * 16) * 2;
#pragma unroll
            for (int mi = 0; mi < 4; mi++)
                ldsm4(af[mi], As_u + a_off + kboff + (uint32_t)(mi * 16 * ROWH) * 2);
#pragma unroll
            for (int np = 0; np < 2; np++)
                ldsm4(bf[np], Bs_u + b_off + kboff + (uint32_t)(np * 16 * ROWH) * 2);
#pragma unroll
            for (int mi = 0; mi < 4; mi++)
#pragma unroll
                for (int ni = 0; ni < 4; ni++)
                    mma_f16(acc[mi][ni], af[mi], &bf[ni >> 1][(ni & 1) * 2]);
        }
        __syncthreads();
        sbuf++; if (sbuf >= NSTAGE) sbuf = 0;
    }

#pragma unroll
    for (int mi = 0; mi < 4; mi++) {
        int mA = m0 + wm + mi * 16 + g;
#pragma unroll
        for (int ni = 0; ni < 4; ni++) {
            int n = n0 + wn + ni * 8 + 2 * q;
            float2 v0 = make_float2(acc[mi][ni][0], acc[mi][ni][1]);
            float2 v1 = make_float2(acc[mi][ni][2], acc[mi][ni][3]);
            if (MODE == 1) {
                *(float2*)(C + (size_t)mA * Ndim + n) = v0;
                *(float2*)(C + (size_t)(mA + 8) * Ndim + n) = v1;
            } else {
                int sel = n >> 10;
                int h   = (n >> 6) & (NH - 1);
                int hd  = n & (HDIM - 1);
                float* dst = (sel == 0) ? g_Q : (sel == 1) ? g_K : g_V;
                int b0r = mA >> 12, l0 = mA & (LL - 1);
                int b1r = (mA + 8) >> 12, l1 = (mA + 8) & (LL - 1);
                *(float2*)(dst + ((size_t)(b0r * NH + h) * LL + l0) * HDIM + hd) = v0;
                *(float2*)(dst + ((size_t)(b1r * NH + h) * LL + l1) * HDIM + hd) = v1;
            }
        }
    }
}

// ---------------------------------------------------------------------------
// RoPE (in-place on g_Q and g_K). One warp per 64-float row.
// ---------------------------------------------------------------------------
__global__ void rope_kernel()
{
    const int nrows = BB * NH * LL;
    int gw   = (blockIdx.x * blockDim.x + threadIdx.x) >> 5;
    int lane = threadIdx.x & 31;

    float* buf = (gw < nrows) ? g_Q : g_K;
    int row = (gw < nrows) ? gw : gw - nrows;
    int l   = row & (LL - 1);

    float* p = buf + (size_t)row * HDIM;
    float2 xv = *(const float2*)(p + 2 * lane);

    float freq = expf(-(float)lane * (9.210340371976184f / 32.0f));
    float tt = (float)l * freq;
    float c = cosf(tt), s = sinf(tt);

    float o1 = xv.x * c - xv.y * s;
    float o2 = xv.y * c + xv.x * s;
    __syncwarp();
    p[lane]      = o1;
    p[lane + 32] = o2;
}

// ---------------------------------------------------------------------------
// Block-local causal attention (fp32 compute, fp16 output for out-proj).
// ---------------------------------------------------------------------------
__global__ __launch_bounds__(256, 1)
void attn_kernel()
{
    extern __shared__ float sm[];
    float4* Ks4 = (float4*)sm;
    float4* Vs4 = (float4*)(sm + BSZ * HDIM);

    int cta = blockIdx.x;
    int nb  = cta & (NBLK - 1);
    int bh  = cta >> 4;
    int rowbase = bh * LL + nb * BSZ;

    const float4* Kg = (const float4*)(g_K + (size_t)rowbase * HDIM);
    const float4* Vg = (const float4*)(g_V + (size_t)rowbase * HDIM);
    for (int idx = threadIdx.x; idx < BSZ * HDIM / 4; idx += 256) {
        Ks4[idx] = Kg[idx];
        Vs4[idx] = Vg[idx];
    }

    const int i = threadIdx.x;
    float q[64];
    const float4* Qg = (const float4*)(g_Q + (size_t)(rowbase + i) * HDIM);
#pragma unroll
    for (int d = 0; d < 16; d++) ((float4*)q)[d] = Qg[d];
    __syncthreads();

    float mmax = -1e30f, lsum = 0.f;
    float acc[64];
#pragma unroll
    for (int d = 0; d < 64; d++) acc[d] = 0.f;

    const int jmax = i | 31;
    for (int j = 0; j <= jmax; j++) {
        float s = 0.f;
#pragma unroll
        for (int d = 0; d < 16; d++) {
            float4 k4 = Ks4[j * 16 + d];
            s += q[4*d+0] * k4.x + q[4*d+1] * k4.y
               + q[4*d+2] * k4.z + q[4*d+3] * k4.w;
        }
        s *= 0.125f;
        if (j <= i) {
            if (s <= mmax) {
                float p = __expf(s - mmax);
                lsum += p;
#pragma unroll
                for (int d = 0; d < 16; d++) {
                    float4 v4 = Vs4[j * 16 + d];
                    acc[4*d+0] += p * v4.x;
                    acc[4*d+1] += p * v4.y;
                    acc[4*d+2] += p * v4.z;
                    acc[4*d+3] += p * v4.w;
                }
            } else {
                float cc = __expf(mmax - s);
                mmax = s;
                lsum = lsum * cc + 1.f;
#pragma unroll
                for (int d = 0; d < 16; d++) {
                    float4 v4 = Vs4[j * 16 + d];
                    acc[4*d+0] = acc[4*d+0] * cc + v4.x;
                    acc[4*d+1] = acc[4*d+1] * cc + v4.y;
                    acc[4*d+2] = acc[4*d+2] * cc + v4.z;
                    acc[4*d+3] = acc[4*d+3] * cc + v4.w;
                }
            }
        }
    }

    float inv = 1.f / lsum;
    int b = bh >> 4;
    int h = bh & (NH - 1);
    __half* Og = g_Oh + (size_t)(b * LL + nb * BSZ + i) * DD + h * HDIM;
#pragma unroll
    for (int d = 0; d < 16; d++) {
        __half2 h0 = __floats2half2_rn(acc[4*d+0] * inv, acc[4*d+1] * inv);
        __half2 h1 = __floats2half2_rn(acc[4*d+2] * inv, acc[4*d+3] * inv);
        *(uint2*)(Og + 4 * d) = make_uint2(*(unsigned*)&h0, *(unsigned*)&h1);
    }
}

// ---------------------------------------------------------------------------
extern "C" void kernel_launch(void* const* d_in, const int* in_sizes, int n_in,
                              void* d_out, int out_size)
{
    const float* x    = (const float*)d_in[0];
    const float* Wqkv = (const float*)d_in[1];
    const float* Wout = (const float*)d_in[2];
    float* out = (float*)d_out;

    void *Oh = nullptr, *Xh = nullptr, *Wqh = nullptr, *Woh = nullptr;
    cudaGetSymbolAddress(&Oh, g_Oh);
    cudaGetSymbolAddress(&Xh, g_Xh);
    cudaGetSymbolAddress(&Wqh, g_Wqkvh);
    cudaGetSymbolAddress(&Woh, g_Wouth);

    cudaFuncSetAttribute(mm_f16<0>, cudaFuncAttributeMaxDynamicSharedMemorySize, GEMM_SMEM);
    cudaFuncSetAttribute(mm_f16<1>, cudaFuncAttributeMaxDynamicSharedMemorySize, GEMM_SMEM);
    cudaFuncSetAttribute(attn_kernel, cudaFuncAttributeMaxDynamicSharedMemorySize,
                         2 * BSZ * HDIM * (int)sizeof(float));

    // 0) fp32 -> fp16 conversion of x, Wqkv, Wout
    {
        int n4x = MR * DD / 4, n4q = 3 * DD * DD / 4, n4o = DD * DD / 4;
        f2h_kernel<<<(n4x + 255) / 256, 256>>>((const float4*)x, (uint2*)Xh, n4x);
        f2h_kernel<<<(n4q + 255) / 256, 256>>>((const float4*)Wqkv, (uint2*)Wqh, n4q);
        f2h_kernel<<<(n4o + 255) / 256, 256>>>((const float4*)Wout, (uint2*)Woh, n4o);
    }

    // 1) QKV projection (fp16 tensor cores), scattered into [B,H,L,HD] Q/K/V
    mm_f16<0><<<dim3(3 * DD / 128, MR / 128), 256, GEMM_SMEM>>>(
        (const __half*)Xh, (const __half*)Wqh, nullptr, DD, 3 * DD);

    // 2) RoPE on Q and K (in place)
    rope_kernel<<<(2 * BB * NH * LL) / 8, 256>>>();

    // 3) Block-local causal attention -> g_Oh (fp16) in [B,L,D]
    attn_kernel<<<BB * NH * NBLK, 256, 2 * BSZ * HDIM * (int)sizeof(float)>>>();

    // 4) Output projection (fp16 tensor cores)
    mm_f16<1><<<dim3(DD / 128, MR / 128), 256, GEMM_SMEM>>>(
        (const __half*)Oh, (const __half*)Woh, out, DD, DD);
}

// round 8
// speedup vs baseline: 3.1312x; 3.1312x over previous
#include <cuda_runtime.h>
#include <cuda_fp16.h>
#include <math.h>
#include <cstdint>

#define BB   2
#define LL   4096
#define DD   1024
#define NH   16
#define HDIM 64
#define BSZ  256
#define NBLK (LL / BSZ)     // 16
#define MR   (BB * LL)      // 8192

// Scratch (allocation-free, __device__ globals) — all fp16
__device__ __half g_Qh[BB * NH * LL * HDIM];
__device__ __half g_Kh[BB * NH * LL * HDIM];
__device__ __half g_Vh[BB * NH * LL * HDIM];
__device__ __half g_Oh[MR * DD];
__device__ __half g_Xh[MR * DD];
__device__ __half g_Wqkvh[3 * DD * DD];
__device__ __half g_Wouth[DD * DD];

// ---------------------------------------------------------------------------
// helpers
// ---------------------------------------------------------------------------
__device__ __forceinline__ uint32_t smem_u32(const void* p) {
    uint32_t a;
    asm("{ .reg .u64 t; cvta.to.shared.u64 t, %1; cvt.u32.u64 %0, t; }" : "=r"(a) : "l"(p));
    return a;
}
__device__ __forceinline__ void cp16(void* smem_dst, const void* gmem_src) {
    unsigned s = (unsigned)__cvta_generic_to_shared(smem_dst);
    asm volatile("cp.async.cg.shared.global [%0], [%1], 16;\n" :: "r"(s), "l"(gmem_src));
}
__device__ __forceinline__ void cp_commit() { asm volatile("cp.async.commit_group;\n"); }
template <int N>
__device__ __forceinline__ void cp_wait() { asm volatile("cp.async.wait_group %0;\n" :: "n"(N)); }

__device__ __forceinline__ void ldsm4(unsigned* r, uint32_t addr) {
    asm volatile("ldmatrix.sync.aligned.m8n8.x4.shared.b16 {%0,%1,%2,%3}, [%4];"
                 : "=r"(r[0]), "=r"(r[1]), "=r"(r[2]), "=r"(r[3]) : "r"(addr));
}
__device__ __forceinline__ void ldsm4t(unsigned* r, uint32_t addr) {
    asm volatile("ldmatrix.sync.aligned.m8n8.x4.trans.shared.b16 {%0,%1,%2,%3}, [%4];"
                 : "=r"(r[0]), "=r"(r[1]), "=r"(r[2]), "=r"(r[3]) : "r"(addr));
}
__device__ __forceinline__ void mma_f16(float* d, const unsigned* a, const unsigned* b) {
    asm volatile(
        "mma.sync.aligned.m16n8k16.row.col.f32.f16.f16.f32 "
        "{%0,%1,%2,%3}, {%4,%5,%6,%7}, {%8,%9}, {%0,%1,%2,%3};\n"
        : "+f"(d[0]), "+f"(d[1]), "+f"(d[2]), "+f"(d[3])
        : "r"(a[0]), "r"(a[1]), "r"(a[2]), "r"(a[3]),
          "r"(b[0]), "r"(b[1]));
}
__device__ __forceinline__ unsigned pack_h2(float a, float b) {
    __half2 h = __floats2half2_rn(a, b);
    return *(unsigned*)&h;
}

// ---------------------------------------------------------------------------
// Pre-pass: fp32 -> fp16
// ---------------------------------------------------------------------------
__global__ void f2h_kernel(const float4* __restrict__ src, uint2* __restrict__ dst, int n4)
{
    int i = blockIdx.x * blockDim.x + threadIdx.x;
    if (i < n4) {
        float4 v = src[i];
        __half2 h0 = __floats2half2_rn(v.x, v.y);
        __half2 h1 = __floats2half2_rn(v.z, v.w);
        dst[i] = make_uint2(*(unsigned*)&h0, *(unsigned*)&h1);
    }
}

// ---------------------------------------------------------------------------
// fp16 tensor-core GEMM: C[M,N] = A[M,K]*B[N,K]^T, fp32 acc.
// CTA 128x128, BK=32, 8 warps, warp 64x32, ldmatrix.x4, 3-stage cp.async.
// MODE 0: fp16 scatter into g_Qh/g_Kh/g_Vh; MODE 1: fp32 row-major C.
// ---------------------------------------------------------------------------
#define ROWH   40
#define TILE_H (128 * ROWH)
#define STAGE_H (2 * TILE_H)
#define NSTAGE 3
#define GEMM_SMEM (NSTAGE * STAGE_H * 2)   // 61440 B

template <int MODE>
__global__ __launch_bounds__(256, 2)
void mm_f16(const __half* __restrict__ A, const __half* __restrict__ Bm,
            float* __restrict__ C, int Kdim, int Ndim)
{
    extern __shared__ __half smh[];
    const uint32_t smem_base = smem_u32(smh);

    const int m0 = blockIdx.y * 128;
    const int n0 = blockIdx.x * 128;
    const int t  = threadIdx.x;
    const int warp = t >> 5, lane = t & 31;
    const int wm = (warp >> 2) * 64;
    const int wn = (warp & 3) * 32;
    const int g = lane >> 2;
    const int q = lane & 3;

    float acc[4][4][4];
#pragma unroll
    for (int i = 0; i < 4; i++)
#pragma unroll
        for (int j = 0; j < 4; j++)
#pragma unroll
            for (int r = 0; r < 4; r++) acc[i][j][r] = 0.f;

    const uint32_t a_off = (uint32_t)((wm + (lane & 15)) * ROWH + (lane >> 4) * 8) * 2;
    const uint32_t b_off = (uint32_t)((wn + (lane & 7) + ((lane >> 4) << 3)) * ROWH
                                      + ((lane >> 3) & 1) * 8) * 2;

    const int KT = Kdim >> 5;

    auto prefetch = [&](int kt, int s) {
        __half* As = smh + s * STAGE_H;
        __half* Bs = As + TILE_H;
        const int k0 = kt << 5;
#pragma unroll
        for (int u = 0; u < 2; u++) {
            int idx = t + u * 256;
            int row = idx >> 2, c8 = (idx & 3) << 3;
            cp16(As + row * ROWH + c8, A + (size_t)(m0 + row) * Kdim + k0 + c8);
        }
#pragma unroll
        for (int u = 0; u < 2; u++) {
            int idx = t + u * 256;
            int row = idx >> 2, c8 = (idx & 3) << 3;
            cp16(Bs + row * ROWH + c8, Bm + (size_t)(n0 + row) * Kdim + k0 + c8);
        }
    };

    prefetch(0, 0); cp_commit();
    prefetch(1, 1); cp_commit();

    int sbuf = 0;
    for (int kt = 0; kt < KT; kt++) {
        if (kt + 1 < KT) cp_wait<1>(); else cp_wait<0>();
        __syncthreads();

        if (kt + 2 < KT) {
            int s2 = sbuf + 2; if (s2 >= NSTAGE) s2 -= NSTAGE;
            prefetch(kt + 2, s2);
            cp_commit();
        }

        const uint32_t As_u = smem_base + (uint32_t)(sbuf * STAGE_H) * 2;
        const uint32_t Bs_u = As_u + TILE_H * 2;

#pragma unroll
        for (int ks = 0; ks < 2; ks++) {
            unsigned af[4][4], bf[2][4];
            const uint32_t kboff = (uint32_t)(ks * 16) * 2;
#pragma unroll
            for (int mi = 0; mi < 4; mi++)
                ldsm4(af[mi], As_u + a_off + kboff + (uint32_t)(mi * 16 * ROWH) * 2);
#pragma unroll
            for (int np = 0; np < 2; np++)
                ldsm4(bf[np], Bs_u + b_off + kboff + (uint32_t)(np * 16 * ROWH) * 2);
#pragma unroll
            for (int mi = 0; mi < 4; mi++)
#pragma unroll
                for (int ni = 0; ni < 4; ni++)
                    mma_f16(acc[mi][ni], af[mi], &bf[ni >> 1][(ni & 1) * 2]);
        }
        __syncthreads();
        sbuf++; if (sbuf >= NSTAGE) sbuf = 0;
    }

#pragma unroll
    for (int mi = 0; mi < 4; mi++) {
        int mA = m0 + wm + mi * 16 + g;
#pragma unroll
        for (int ni = 0; ni < 4; ni++) {
            int n = n0 + wn + ni * 8 + 2 * q;
            if (MODE == 1) {
                float2 v0 = make_float2(acc[mi][ni][0], acc[mi][ni][1]);
                float2 v1 = make_float2(acc[mi][ni][2], acc[mi][ni][3]);
                *(float2*)(C + (size_t)mA * Ndim + n) = v0;
                *(float2*)(C + (size_t)(mA + 8) * Ndim + n) = v1;
            } else {
                int sel = n >> 10;
                int h   = (n >> 6) & (NH - 1);
                int hd  = n & (HDIM - 1);
                __half* dst = (sel == 0) ? g_Qh : (sel == 1) ? g_Kh : g_Vh;
                int b0r = mA >> 12, l0 = mA & (LL - 1);
                int b1r = (mA + 8) >> 12, l1 = (mA + 8) & (LL - 1);
                __half2 h0 = __floats2half2_rn(acc[mi][ni][0], acc[mi][ni][1]);
                __half2 h1 = __floats2half2_rn(acc[mi][ni][2], acc[mi][ni][3]);
                *(__half2*)(dst + ((size_t)(b0r * NH + h) * LL + l0) * HDIM + hd) = h0;
                *(__half2*)(dst + ((size_t)(b1r * NH + h) * LL + l1) * HDIM + hd) = h1;
            }
        }
    }
}

// ---------------------------------------------------------------------------
// Tensor-core block-local causal flash attention + fused RoPE.
// One CTA per (b,h,block): Q/K/V fp16 tiles in smem (72-half padded rows),
// RoPE applied in-smem (read row to regs FIRST, then write — the overlap
// bug of round 7), warp w owns rows [32w,32w+32), iterates chunks c<=w.
// ---------------------------------------------------------------------------
#define AROW 72
#define ATILE (BSZ * AROW)                 // halves (18432)
#define ATTN_SMEM (3 * ATILE * 2)          // 110592 B

__global__ __launch_bounds__(256, 1)
void attn_tc()
{
    extern __shared__ __half sh[];
    __half* Qs = sh;
    __half* Ks = sh + ATILE;
    __half* Vs = sh + 2 * ATILE;
    const uint32_t Qs_u = smem_u32(Qs);
    const uint32_t Ks_u = Qs_u + ATILE * 2;
    const uint32_t Vs_u = Qs_u + 2 * ATILE * 2;

    const int cta = blockIdx.x;
    const int nb  = cta & (NBLK - 1);
    const int bh  = cta >> 4;
    const int b   = bh >> 4, h = bh & (NH - 1);
    const size_t rowbase = (size_t)bh * LL + (size_t)nb * BSZ;

    const int t = threadIdx.x;
    const int warp = t >> 5, lane = t & 31;

    // ---- load Q,K,V tiles (fp16, 128B rows) ----
    {
        const __half* Qg = g_Qh + rowbase * HDIM;
        const __half* Kg = g_Kh + rowbase * HDIM;
        const __half* Vg = g_Vh + rowbase * HDIM;
        for (int idx = t; idx < BSZ * HDIM / 8; idx += 256) {
            int row = idx >> 3, c8 = (idx & 7) << 3;
            cp16(Qs + row * AROW + c8, Qg + row * HDIM + c8);
            cp16(Ks + row * AROW + c8, Kg + row * HDIM + c8);
            cp16(Vs + row * AROW + c8, Vg + row * HDIM + c8);
        }
        cp_commit(); cp_wait<0>();
        __syncthreads();
    }

    // ---- RoPE in-smem on Q and K: read full row into regs, then write ----
    {
        const int row = t;
        const float pos = (float)(nb * BSZ + row);
        float cs[32], sn[32];
#pragma unroll
        for (int i = 0; i < 32; i++) {
            float ang = pos * __expf(-(float)i * (9.210340371976184f / 32.0f));
            __sincosf(ang, &sn[i], &cs[i]);
        }
#pragma unroll
        for (int pass = 0; pass < 2; pass++) {
            __half* p = (pass == 0 ? Qs : Ks) + row * AROW;
            float xv[64];
#pragma unroll
            for (int d = 0; d < 32; d++) {
                __half2 v = ((__half2*)p)[d];
                xv[2 * d]     = __half2float(v.x);
                xv[2 * d + 1] = __half2float(v.y);
            }
#pragma unroll
            for (int i = 0; i < 32; i += 2) {
                *(__half2*)(p + i) = __floats2half2_rn(
                    xv[2 * i]     * cs[i]     - xv[2 * i + 1] * sn[i],
                    xv[2 * i + 2] * cs[i + 1] - xv[2 * i + 3] * sn[i + 1]);
                *(__half2*)(p + 32 + i) = __floats2half2_rn(
                    xv[2 * i + 1] * cs[i]     + xv[2 * i]     * sn[i],
                    xv[2 * i + 3] * cs[i + 1] + xv[2 * i + 2] * sn[i + 1]);
            }
        }
        __syncthreads();
    }

    // ---- Q fragments (held in registers) ----
    unsigned qf[2][4][4];
#pragma unroll
    for (int mt = 0; mt < 2; mt++)
#pragma unroll
        for (int ks = 0; ks < 4; ks++)
            ldsm4(qf[mt][ks], Qs_u + (uint32_t)(((warp * 32 + mt * 16 + (lane & 15)) * AROW
                                                 + ks * 16 + (lane >> 4) * 8) * 2));

    float o[2][8][4];
#pragma unroll
    for (int mt = 0; mt < 2; mt++)
#pragma unroll
        for (int nd = 0; nd < 8; nd++)
#pragma unroll
            for (int e = 0; e < 4; e++) o[mt][nd][e] = 0.f;

    float mrow[2][2] = {{-1e30f, -1e30f}, {-1e30f, -1e30f}};
    float lrow[2][2] = {{0.f, 0.f}, {0.f, 0.f}};

    const int g  = lane >> 2;
    const int q2 = (lane & 3) * 2;

    for (int c = 0; c <= warp; c++) {
        // ---- S chunk: [32 rows x 32 keys] = Q(32x64) * K(32x64)^T ----
        float s[2][4][4];
#pragma unroll
        for (int mt = 0; mt < 2; mt++)
#pragma unroll
            for (int nt = 0; nt < 4; nt++)
#pragma unroll
                for (int e = 0; e < 4; e++) s[mt][nt][e] = 0.f;

#pragma unroll
        for (int ks = 0; ks < 4; ks++) {
            unsigned bf0[4], bf1[4];
            uint32_t base = Ks_u + (uint32_t)(((c * 32 + (lane & 7) + ((lane >> 4) << 3)) * AROW
                                               + ks * 16 + ((lane >> 3) & 1) * 8) * 2);
            ldsm4(bf0, base);
            ldsm4(bf1, base + (uint32_t)(16 * AROW * 2));
#pragma unroll
            for (int mt = 0; mt < 2; mt++) {
                mma_f16(s[mt][0], qf[mt][ks], &bf0[0]);
                mma_f16(s[mt][1], qf[mt][ks], &bf0[2]);
                mma_f16(s[mt][2], qf[mt][ks], &bf1[0]);
                mma_f16(s[mt][3], qf[mt][ks], &bf1[2]);
            }
        }

        // ---- scale + causal mask + online softmax ----
#pragma unroll
        for (int mt = 0; mt < 2; mt++) {
#pragma unroll
            for (int nt = 0; nt < 4; nt++)
#pragma unroll
                for (int e = 0; e < 4; e++) s[mt][nt][e] *= 0.125f;

            if (c == warp) {
                const int rA = 16 * mt + g, rB = rA + 8;
#pragma unroll
                for (int nt = 0; nt < 4; nt++) {
                    int col = 8 * nt + q2;
                    if (col     > rA) s[mt][nt][0] = -1e30f;
                    if (col + 1 > rA) s[mt][nt][1] = -1e30f;
                    if (col     > rB) s[mt][nt][2] = -1e30f;
                    if (col + 1 > rB) s[mt][nt][3] = -1e30f;
                }
            }

            float mxA = -1e30f, mxB = -1e30f;
#pragma unroll
            for (int nt = 0; nt < 4; nt++) {
                mxA = fmaxf(mxA, fmaxf(s[mt][nt][0], s[mt][nt][1]));
                mxB = fmaxf(mxB, fmaxf(s[mt][nt][2], s[mt][nt][3]));
            }
            mxA = fmaxf(mxA, __shfl_xor_sync(0xFFFFFFFFu, mxA, 1));
            mxA = fmaxf(mxA, __shfl_xor_sync(0xFFFFFFFFu, mxA, 2));
            mxB = fmaxf(mxB, __shfl_xor_sync(0xFFFFFFFFu, mxB, 1));
            mxB = fmaxf(mxB, __shfl_xor_sync(0xFFFFFFFFu, mxB, 2));

            float newA = fmaxf(mrow[mt][0], mxA);
            float newB = fmaxf(mrow[mt][1], mxB);
            float fA = __expf(mrow[mt][0] - newA);
            float fB = __expf(mrow[mt][1] - newB);
            mrow[mt][0] = newA; mrow[mt][1] = newB;

            float sumA = 0.f, sumB = 0.f;
#pragma unroll
            for (int nt = 0; nt < 4; nt++) {
                s[mt][nt][0] = __expf(s[mt][nt][0] - newA);
                s[mt][nt][1] = __expf(s[mt][nt][1] - newA);
                s[mt][nt][2] = __expf(s[mt][nt][2] - newB);
                s[mt][nt][3] = __expf(s[mt][nt][3] - newB);
                sumA += s[mt][nt][0] + s[mt][nt][1];
                sumB += s[mt][nt][2] + s[mt][nt][3];
            }
            sumA += __shfl_xor_sync(0xFFFFFFFFu, sumA, 1);
            sumA += __shfl_xor_sync(0xFFFFFFFFu, sumA, 2);
            sumB += __shfl_xor_sync(0xFFFFFFFFu, sumB, 1);
            sumB += __shfl_xor_sync(0xFFFFFFFFu, sumB, 2);
            lrow[mt][0] = lrow[mt][0] * fA + sumA;
            lrow[mt][1] = lrow[mt][1] * fB + sumB;

#pragma unroll
            for (int nd = 0; nd < 8; nd++) {
                o[mt][nd][0] *= fA; o[mt][nd][1] *= fA;
                o[mt][nd][2] *= fB; o[mt][nd][3] *= fB;
            }
        }

        // ---- PV: O[32,64] += P[32,32] * V[32,64] (B via ldmatrix.trans) ----
#pragma unroll
        for (int pt = 0; pt < 2; pt++) {
            unsigned vb[4][4];
#pragma unroll
            for (int nd16 = 0; nd16 < 4; nd16++) {
                uint32_t addr = Vs_u + (uint32_t)(((c * 32 + pt * 16 + (lane & 7)
                                                   + (((lane >> 3) & 1) << 3)) * AROW
                                                  + nd16 * 16 + (lane >> 4) * 8) * 2);
                ldsm4t(vb[nd16], addr);
            }
#pragma unroll
            for (int mt = 0; mt < 2; mt++) {
                unsigned pa[4];
                pa[0] = pack_h2(s[mt][2 * pt][0],     s[mt][2 * pt][1]);
                pa[1] = pack_h2(s[mt][2 * pt][2],     s[mt][2 * pt][3]);
                pa[2] = pack_h2(s[mt][2 * pt + 1][0], s[mt][2 * pt + 1][1]);
                pa[3] = pack_h2(s[mt][2 * pt + 1][2], s[mt][2 * pt + 1][3]);
#pragma unroll
                for (int nd16 = 0; nd16 < 4; nd16++) {
                    mma_f16(o[mt][2 * nd16],     pa, &vb[nd16][0]);
                    mma_f16(o[mt][2 * nd16 + 1], pa, &vb[nd16][2]);
                }
            }
        }
    }

    // ---- normalize + store O (fp16, [B,L,D] layout) ----
#pragma unroll
    for (int mt = 0; mt < 2; mt++) {
        float iA = 1.f / lrow[mt][0];
        float iB = 1.f / lrow[mt][1];
        const int rA = warp * 32 + mt * 16 + g;
        size_t baseA = ((size_t)(b * LL) + nb * BSZ + rA) * DD + h * HDIM;
        size_t baseB = baseA + (size_t)8 * DD;
#pragma unroll
        for (int nd = 0; nd < 8; nd++) {
            *(__half2*)(g_Oh + baseA + 8 * nd + q2) =
                __floats2half2_rn(o[mt][nd][0] * iA, o[mt][nd][1] * iA);
            *(__half2*)(g_Oh + baseB + 8 * nd + q2) =
                __floats2half2_rn(o[mt][nd][2] * iB, o[mt][nd][3] * iB);
        }
    }
}

// ---------------------------------------------------------------------------
extern "C" void kernel_launch(void* const* d_in, const int* in_sizes, int n_in,
                              void* d_out, int out_size)
{
    const float* x    = (const float*)d_in[0];
    const float* Wqkv = (const float*)d_in[1];
    const float* Wout = (const float*)d_in[2];
    float* out = (float*)d_out;

    void *Oh = nullptr, *Xh = nullptr, *Wqh = nullptr, *Woh = nullptr;
    cudaGetSymbolAddress(&Oh, g_Oh);
    cudaGetSymbolAddress(&Xh, g_Xh);
    cudaGetSymbolAddress(&Wqh, g_Wqkvh);
    cudaGetSymbolAddress(&Woh, g_Wouth);

    cudaFuncSetAttribute(mm_f16<0>, cudaFuncAttributeMaxDynamicSharedMemorySize, GEMM_SMEM);
    cudaFuncSetAttribute(mm_f16<1>, cudaFuncAttributeMaxDynamicSharedMemorySize, GEMM_SMEM);
    cudaFuncSetAttribute(attn_tc, cudaFuncAttributeMaxDynamicSharedMemorySize, ATTN_SMEM);

    // 0) fp32 -> fp16 conversion of x, Wqkv, Wout
    {
        int n4x = MR * DD / 4, n4q = 3 * DD * DD / 4, n4o = DD * DD / 4;
        f2h_kernel<<<(n4x + 255) / 256, 256>>>((const float4*)x, (uint2*)Xh, n4x);
        f2h_kernel<<<(n4q + 255) / 256, 256>>>((const float4*)Wqkv, (uint2*)Wqh, n4q);
        f2h_kernel<<<(n4o + 255) / 256, 256>>>((const float4*)Wout, (uint2*)Woh, n4o);
    }

    // 1) QKV projection (fp16 tensor cores) -> fp16 Q/K/V in [B,H,L,HD]
    mm_f16<0><<<dim3(3 * DD / 128, MR / 128), 256, GEMM_SMEM>>>(
        (const __half*)Xh, (const __half*)Wqh, nullptr, DD, 3 * DD);

    // 2) Fused RoPE + tensor-core flash attention -> g_Oh fp16 [B,L,D]
    attn_tc<<<BB * NH * NBLK, 256, ATTN_SMEM>>>();

    // 3) Output projection (fp16 tensor cores) -> fp32 out
    mm_f16<1><<<dim3(DD / 128, MR / 128), 256, GEMM_SMEM>>>(
        (const __half*)Oh, (const __half*)Woh, out, DD, DD);
}

// round 9
// speedup vs baseline: 3.5025x; 1.1186x over previous
#include <cuda_runtime.h>
#include <cuda_fp16.h>
#include <math.h>
#include <cstdint>

#define BB   2
#define LL   4096
#define DD   1024
#define NH   16
#define HDIM 64
#define BSZ  256
#define NBLK (LL / BSZ)     // 16
#define MR   (BB * LL)      // 8192

// Scratch (allocation-free, __device__ globals) — all fp16
__device__ __half g_Qh[BB * NH * LL * HDIM];
__device__ __half g_Kh[BB * NH * LL * HDIM];
__device__ __half g_Vh[BB * NH * LL * HDIM];
__device__ __half g_Oh[MR * DD];
__device__ __half g_Xh[MR * DD];
__device__ __half g_Wqkvh[3 * DD * DD];
__device__ __half g_Wouth[DD * DD];

// ---------------------------------------------------------------------------
// helpers
// ---------------------------------------------------------------------------
__device__ __forceinline__ uint32_t smem_u32(const void* p) {
    uint32_t a;
    asm("{ .reg .u64 t; cvta.to.shared.u64 t, %1; cvt.u32.u64 %0, t; }" : "=r"(a) : "l"(p));
    return a;
}
__device__ __forceinline__ void cp16(void* smem_dst, const void* gmem_src) {
    unsigned s = (unsigned)__cvta_generic_to_shared(smem_dst);
    asm volatile("cp.async.cg.shared.global [%0], [%1], 16;\n" :: "r"(s), "l"(gmem_src));
}
__device__ __forceinline__ void cp_commit() { asm volatile("cp.async.commit_group;\n"); }
template <int N>
__device__ __forceinline__ void cp_wait() { asm volatile("cp.async.wait_group %0;\n" :: "n"(N)); }

__device__ __forceinline__ void ldsm4(unsigned* r, uint32_t addr) {
    asm volatile("ldmatrix.sync.aligned.m8n8.x4.shared.b16 {%0,%1,%2,%3}, [%4];"
                 : "=r"(r[0]), "=r"(r[1]), "=r"(r[2]), "=r"(r[3]) : "r"(addr));
}
__device__ __forceinline__ void ldsm4t(unsigned* r, uint32_t addr) {
    asm volatile("ldmatrix.sync.aligned.m8n8.x4.trans.shared.b16 {%0,%1,%2,%3}, [%4];"
                 : "=r"(r[0]), "=r"(r[1]), "=r"(r[2]), "=r"(r[3]) : "r"(addr));
}
__device__ __forceinline__ void mma_f16(float* d, const unsigned* a, const unsigned* b) {
    asm volatile(
        "mma.sync.aligned.m16n8k16.row.col.f32.f16.f16.f32 "
        "{%0,%1,%2,%3}, {%4,%5,%6,%7}, {%8,%9}, {%0,%1,%2,%3};\n"
        : "+f"(d[0]), "+f"(d[1]), "+f"(d[2]), "+f"(d[3])
        : "r"(a[0]), "r"(a[1]), "r"(a[2]), "r"(a[3]),
          "r"(b[0]), "r"(b[1]));
}
__device__ __forceinline__ unsigned pack_h2(float a, float b) {
    __half2 h = __floats2half2_rn(a, b);
    return *(unsigned*)&h;
}

// ---------------------------------------------------------------------------
// Pre-pass: fp32 -> fp16
// ---------------------------------------------------------------------------
__global__ void f2h_kernel(const float4* __restrict__ src, uint2* __restrict__ dst, int n4)
{
    int i = blockIdx.x * blockDim.x + threadIdx.x;
    if (i < n4) {
        float4 v = src[i];
        __half2 h0 = __floats2half2_rn(v.x, v.y);
        __half2 h1 = __floats2half2_rn(v.z, v.w);
        dst[i] = make_uint2(*(unsigned*)&h0, *(unsigned*)&h1);
    }
}

// ---------------------------------------------------------------------------
// fp16 tensor-core GEMM v2: C[M,N] = A[M,K]*B[N,K]^T, fp32 acc.
// CTA 128x128, BK=64, 8 warps (2x4), warp 64x32, ldmatrix.x4,
// 2-stage cp.async, ONE barrier per k-iteration (wait -> sync -> prefetch
// next stage -> compute). SMEM rows stride 72 halves (conflict-free ldmatrix).
// MODE 0: fp16 scatter into g_Qh/g_Kh/g_Vh; MODE 1: fp32 row-major C.
// ---------------------------------------------------------------------------
#define ROWH   72
#define TILE_H (128 * ROWH)                // 9216 halves per operand tile
#define STAGE_H (2 * TILE_H)               // 18432 halves = 36864 B
#define GEMM_SMEM (2 * STAGE_H * 2)        // 73728 B

template <int MODE>
__global__ __launch_bounds__(256, 2)
void mm_f16(const __half* __restrict__ A, const __half* __restrict__ Bm,
            float* __restrict__ C, int Kdim, int Ndim)
{
    extern __shared__ __half smh[];
    const uint32_t smem_base = smem_u32(smh);

    const int m0 = blockIdx.y * 128;
    const int n0 = blockIdx.x * 128;
    const int t  = threadIdx.x;
    const int warp = t >> 5, lane = t & 31;
    const int wm = (warp >> 2) * 64;
    const int wn = (warp & 3) * 32;
    const int g = lane >> 2;
    const int q = lane & 3;

    float acc[4][4][4];
#pragma unroll
    for (int i = 0; i < 4; i++)
#pragma unroll
        for (int j = 0; j < 4; j++)
#pragma unroll
            for (int r = 0; r < 4; r++) acc[i][j][r] = 0.f;

    const uint32_t a_off = (uint32_t)((wm + (lane & 15)) * ROWH + (lane >> 4) * 8) * 2;
    const uint32_t b_off = (uint32_t)((wn + (lane & 7) + ((lane >> 4) << 3)) * ROWH
                                      + ((lane >> 3) & 1) * 8) * 2;

    const int KT = Kdim >> 6;              // 64-wide k-tiles

    auto prefetch = [&](int kt, int s) {
        __half* As = smh + s * STAGE_H;
        __half* Bs = As + TILE_H;
        const int k0 = kt << 6;
        // 128 rows x 8 chunks (16B) per operand = 1024 chunks, 4 per thread
#pragma unroll
        for (int u = 0; u < 4; u++) {
            int idx = t + u * 256;
            int row = idx >> 3, c8 = (idx & 7) << 3;
            cp16(As + row * ROWH + c8, A + (size_t)(m0 + row) * Kdim + k0 + c8);
        }
#pragma unroll
        for (int u = 0; u < 4; u++) {
            int idx = t + u * 256;
            int row = idx >> 3, c8 = (idx & 7) << 3;
            cp16(Bs + row * ROWH + c8, Bm + (size_t)(n0 + row) * Kdim + k0 + c8);
        }
    };

    prefetch(0, 0);
    cp_commit();

    for (int kt = 0; kt < KT; kt++) {
        const int buf = kt & 1;
        cp_wait<0>();                      // stage `buf` ready
        __syncthreads();                   // all warps done reading stage buf^1

        if (kt + 1 < KT) {
            prefetch(kt + 1, buf ^ 1);     // refill the stage everyone released
            cp_commit();
        }

        const uint32_t As_u = smem_base + (uint32_t)(buf * STAGE_H) * 2;
        const uint32_t Bs_u = As_u + TILE_H * 2;

#pragma unroll
        for (int ks = 0; ks < 4; ks++) {
            unsigned af[4][4], bf[2][4];
            const uint32_t kboff = (uint32_t)(ks * 16) * 2;
#pragma unroll
            for (int mi = 0; mi < 4; mi++)
                ldsm4(af[mi], As_u + a_off + kboff + (uint32_t)(mi * 16 * ROWH) * 2);
#pragma unroll
            for (int np = 0; np < 2; np++)
                ldsm4(bf[np], Bs_u + b_off + kboff + (uint32_t)(np * 16 * ROWH) * 2);
#pragma unroll
            for (int mi = 0; mi < 4; mi++)
#pragma unroll
                for (int ni = 0; ni < 4; ni++)
                    mma_f16(acc[mi][ni], af[mi], &bf[ni >> 1][(ni & 1) * 2]);
        }
    }

#pragma unroll
    for (int mi = 0; mi < 4; mi++) {
        int mA = m0 + wm + mi * 16 + g;
#pragma unroll
        for (int ni = 0; ni < 4; ni++) {
            int n = n0 + wn + ni * 8 + 2 * q;
            if (MODE == 1) {
                float2 v0 = make_float2(acc[mi][ni][0], acc[mi][ni][1]);
                float2 v1 = make_float2(acc[mi][ni][2], acc[mi][ni][3]);
                *(float2*)(C + (size_t)mA * Ndim + n) = v0;
                *(float2*)(C + (size_t)(mA + 8) * Ndim + n) = v1;
            } else {
                int sel = n >> 10;
                int h   = (n >> 6) & (NH - 1);
                int hd  = n & (HDIM - 1);
                __half* dst = (sel == 0) ? g_Qh : (sel == 1) ? g_Kh : g_Vh;
                int b0r = mA >> 12, l0 = mA & (LL - 1);
                int b1r = (mA + 8) >> 12, l1 = (mA + 8) & (LL - 1);
                __half2 h0 = __floats2half2_rn(acc[mi][ni][0], acc[mi][ni][1]);
                __half2 h1 = __floats2half2_rn(acc[mi][ni][2], acc[mi][ni][3]);
                *(__half2*)(dst + ((size_t)(b0r * NH + h) * LL + l0) * HDIM + hd) = h0;
                *(__half2*)(dst + ((size_t)(b1r * NH + h) * LL + l1) * HDIM + hd) = h1;
            }
        }
    }
}

// ---------------------------------------------------------------------------
// Tensor-core block-local causal flash attention + fused RoPE (round-8).
// ---------------------------------------------------------------------------
#define AROW 72
#define ATILE (BSZ * AROW)                 // halves (18432)
#define ATTN_SMEM (3 * ATILE * 2)          // 110592 B

__global__ __launch_bounds__(256, 1)
void attn_tc()
{
    extern __shared__ __half sh[];
    __half* Qs = sh;
    __half* Ks = sh + ATILE;
    __half* Vs = sh + 2 * ATILE;
    const uint32_t Qs_u = smem_u32(Qs);
    const uint32_t Ks_u = Qs_u + ATILE * 2;
    const uint32_t Vs_u = Qs_u + 2 * ATILE * 2;

    const int cta = blockIdx.x;
    const int nb  = cta & (NBLK - 1);
    const int bh  = cta >> 4;
    const int b   = bh >> 4, h = bh & (NH - 1);
    const size_t rowbase = (size_t)bh * LL + (size_t)nb * BSZ;

    const int t = threadIdx.x;
    const int warp = t >> 5, lane = t & 31;

    {
        const __half* Qg = g_Qh + rowbase * HDIM;
        const __half* Kg = g_Kh + rowbase * HDIM;
        const __half* Vg = g_Vh + rowbase * HDIM;
        for (int idx = t; idx < BSZ * HDIM / 8; idx += 256) {
            int row = idx >> 3, c8 = (idx & 7) << 3;
            cp16(Qs + row * AROW + c8, Qg + row * HDIM + c8);
            cp16(Ks + row * AROW + c8, Kg + row * HDIM + c8);
            cp16(Vs + row * AROW + c8, Vg + row * HDIM + c8);
        }
        cp_commit(); cp_wait<0>();
        __syncthreads();
    }

    // RoPE in-smem: read full row to regs first, then write (no overlap).
    {
        const int row = t;
        const float pos = (float)(nb * BSZ + row);
        float cs[32], sn[32];
#pragma unroll
        for (int i = 0; i < 32; i++) {
            float ang = pos * __expf(-(float)i * (9.210340371976184f / 32.0f));
            __sincosf(ang, &sn[i], &cs[i]);
        }
#pragma unroll
        for (int pass = 0; pass < 2; pass++) {
            __half* p = (pass == 0 ? Qs : Ks) + row * AROW;
            float xv[64];
#pragma unroll
            for (int d = 0; d < 32; d++) {
                __half2 v = ((__half2*)p)[d];
                xv[2 * d]     = __half2float(v.x);
                xv[2 * d + 1] = __half2float(v.y);
            }
#pragma unroll
            for (int i = 0; i < 32; i += 2) {
                *(__half2*)(p + i) = __floats2half2_rn(
                    xv[2 * i]     * cs[i]     - xv[2 * i + 1] * sn[i],
                    xv[2 * i + 2] * cs[i + 1] - xv[2 * i + 3] * sn[i + 1]);
                *(__half2*)(p + 32 + i) = __floats2half2_rn(
                    xv[2 * i + 1] * cs[i]     + xv[2 * i]     * sn[i],
                    xv[2 * i + 3] * cs[i + 1] + xv[2 * i + 2] * sn[i + 1]);
            }
        }
        __syncthreads();
    }

    unsigned qf[2][4][4];
#pragma unroll
    for (int mt = 0; mt < 2; mt++)
#pragma unroll
        for (int ks = 0; ks < 4; ks++)
            ldsm4(qf[mt][ks], Qs_u + (uint32_t)(((warp * 32 + mt * 16 + (lane & 15)) * AROW
                                                 + ks * 16 + (lane >> 4) * 8) * 2));

    float o[2][8][4];
#pragma unroll
    for (int mt = 0; mt < 2; mt++)
#pragma unroll
        for (int nd = 0; nd < 8; nd++)
#pragma unroll
            for (int e = 0; e < 4; e++) o[mt][nd][e] = 0.f;

    float mrow[2][2] = {{-1e30f, -1e30f}, {-1e30f, -1e30f}};
    float lrow[2][2] = {{0.f, 0.f}, {0.f, 0.f}};

    const int g  = lane >> 2;
    const int q2 = (lane & 3) * 2;

    for (int c = 0; c <= warp; c++) {
        float s[2][4][4];
#pragma unroll
        for (int mt = 0; mt < 2; mt++)
#pragma unroll
            for (int nt = 0; nt < 4; nt++)
#pragma unroll
                for (int e = 0; e < 4; e++) s[mt][nt][e] = 0.f;

#pragma unroll
        for (int ks = 0; ks < 4; ks++) {
            unsigned bf0[4], bf1[4];
            uint32_t base = Ks_u + (uint32_t)(((c * 32 + (lane & 7) + ((lane >> 4) << 3)) * AROW
                                               + ks * 16 + ((lane >> 3) & 1) * 8) * 2);
            ldsm4(bf0, base);
            ldsm4(bf1, base + (uint32_t)(16 * AROW * 2));
#pragma unroll
            for (int mt = 0; mt < 2; mt++) {
                mma_f16(s[mt][0], qf[mt][ks], &bf0[0]);
                mma_f16(s[mt][1], qf[mt][ks], &bf0[2]);
                mma_f16(s[mt][2], qf[mt][ks], &bf1[0]);
                mma_f16(s[mt][3], qf[mt][ks], &bf1[2]);
            }
        }

#pragma unroll
        for (int mt = 0; mt < 2; mt++) {
#pragma unroll
            for (int nt = 0; nt < 4; nt++)
#pragma unroll
                for (int e = 0; e < 4; e++) s[mt][nt][e] *= 0.125f;

            if (c == warp) {
                const int rA = 16 * mt + g, rB = rA + 8;
#pragma unroll
                for (int nt = 0; nt < 4; nt++) {
                    int col = 8 * nt + q2;
                    if (col     > rA) s[mt][nt][0] = -1e30f;
                    if (col + 1 > rA) s[mt][nt][1] = -1e30f;
                    if (col     > rB) s[mt][nt][2] = -1e30f;
                    if (col + 1 > rB) s[mt][nt][3] = -1e30f;
                }
            }

            float mxA = -1e30f, mxB = -1e30f;
#pragma unroll
            for (int nt = 0; nt < 4; nt++) {
                mxA = fmaxf(mxA, fmaxf(s[mt][nt][0], s[mt][nt][1]));
                mxB = fmaxf(mxB, fmaxf(s[mt][nt][2], s[mt][nt][3]));
            }
            mxA = fmaxf(mxA, __shfl_xor_sync(0xFFFFFFFFu, mxA, 1));
            mxA = fmaxf(mxA, __shfl_xor_sync(0xFFFFFFFFu, mxA, 2));
            mxB = fmaxf(mxB, __shfl_xor_sync(0xFFFFFFFFu, mxB, 1));
            mxB = fmaxf(mxB, __shfl_xor_sync(0xFFFFFFFFu, mxB, 2));

            float newA = fmaxf(mrow[mt][0], mxA);
            float newB = fmaxf(mrow[mt][1], mxB);
            float fA = __expf(mrow[mt][0] - newA);
            float fB = __expf(mrow[mt][1] - newB);
            mrow[mt][0] = newA; mrow[mt][1] = newB;

            float sumA = 0.f, sumB = 0.f;
#pragma unroll
            for (int nt = 0; nt < 4; nt++) {
                s[mt][nt][0] = __expf(s[mt][nt][0] - newA);
                s[mt][nt][1] = __expf(s[mt][nt][1] - newA);
                s[mt][nt][2] = __expf(s[mt][nt][2] - newB);
                s[mt][nt][3] = __expf(s[mt][nt][3] - newB);
                sumA += s[mt][nt][0] + s[mt][nt][1];
                sumB += s[mt][nt][2] + s[mt][nt][3];
            }
            sumA += __shfl_xor_sync(0xFFFFFFFFu, sumA, 1);
            sumA += __shfl_xor_sync(0xFFFFFFFFu, sumA, 2);
            sumB += __shfl_xor_sync(0xFFFFFFFFu, sumB, 1);
            sumB += __shfl_xor_sync(0xFFFFFFFFu, sumB, 2);
            lrow[mt][0] = lrow[mt][0] * fA + sumA;
            lrow[mt][1] = lrow[mt][1] * fB + sumB;

#pragma unroll
            for (int nd = 0; nd < 8; nd++) {
                o[mt][nd][0] *= fA; o[mt][nd][1] *= fA;
                o[mt][nd][2] *= fB; o[mt][nd][3] *= fB;
            }
        }

#pragma unroll
        for (int pt = 0; pt < 2; pt++) {
            unsigned vb[4][4];
#pragma unroll
            for (int nd16 = 0; nd16 < 4; nd16++) {
                uint32_t addr = Vs_u + (uint32_t)(((c * 32 + pt * 16 + (lane & 7)
                                                   + (((lane >> 3) & 1) << 3)) * AROW
                                                  + nd16 * 16 + (lane >> 4) * 8) * 2);
                ldsm4t(vb[nd16], addr);
            }
#pragma unroll
            for (int mt = 0; mt < 2; mt++) {
                unsigned pa[4];
                pa[0] = pack_h2(s[mt][2 * pt][0],     s[mt][2 * pt][1]);
                pa[1] = pack_h2(s[mt][2 * pt][2],     s[mt][2 * pt][3]);
                pa[2] = pack_h2(s[mt][2 * pt + 1][0], s[mt][2 * pt + 1][1]);
                pa[3] = pack_h2(s[mt][2 * pt + 1][2], s[mt][2 * pt + 1][3]);
#pragma unroll
                for (int nd16 = 0; nd16 < 4; nd16++) {
                    mma_f16(o[mt][2 * nd16],     pa, &vb[nd16][0]);
                    mma_f16(o[mt][2 * nd16 + 1], pa, &vb[nd16][2]);
                }
            }
        }
    }

#pragma unroll
    for (int mt = 0; mt < 2; mt++) {
        float iA = 1.f / lrow[mt][0];
        float iB = 1.f / lrow[mt][1];
        const int rA = warp * 32 + mt * 16 + g;
        size_t baseA = ((size_t)(b * LL) + nb * BSZ + rA) * DD + h * HDIM;
        size_t baseB = baseA + (size_t)8 * DD;
#pragma unroll
        for (int nd = 0; nd < 8; nd++) {
            *(__half2*)(g_Oh + baseA + 8 * nd + q2) =
                __floats2half2_rn(o[mt][nd][0] * iA, o[mt][nd][1] * iA);
            *(__half2*)(g_Oh + baseB + 8 * nd + q2) =
                __floats2half2_rn(o[mt][nd][2] * iB, o[mt][nd][3] * iB);
        }
    }
}

// ---------------------------------------------------------------------------
extern "C" void kernel_launch(void* const* d_in, const int* in_sizes, int n_in,
                              void* d_out, int out_size)
{
    const float* x    = (const float*)d_in[0];
    const float* Wqkv = (const float*)d_in[1];
    const float* Wout = (const float*)d_in[2];
    float* out = (float*)d_out;

    void *Oh = nullptr, *Xh = nullptr, *Wqh = nullptr, *Woh = nullptr;
    cudaGetSymbolAddress(&Oh, g_Oh);
    cudaGetSymbolAddress(&Xh, g_Xh);
    cudaGetSymbolAddress(&Wqh, g_Wqkvh);
    cudaGetSymbolAddress(&Woh, g_Wouth);

    cudaFuncSetAttribute(mm_f16<0>, cudaFuncAttributeMaxDynamicSharedMemorySize, GEMM_SMEM);
    cudaFuncSetAttribute(mm_f16<1>, cudaFuncAttributeMaxDynamicSharedMemorySize, GEMM_SMEM);
    cudaFuncSetAttribute(attn_tc, cudaFuncAttributeMaxDynamicSharedMemorySize, ATTN_SMEM);

    // 0) fp32 -> fp16 conversion of x, Wqkv, Wout
    {
        int n4x = MR * DD / 4, n4q = 3 * DD * DD / 4, n4o = DD * DD / 4;
        f2h_kernel<<<(n4x + 255) / 256, 256>>>((const float4*)x, (uint2*)Xh, n4x);
        f2h_kernel<<<(n4q + 255) / 256, 256>>>((const float4*)Wqkv, (uint2*)Wqh, n4q);
        f2h_kernel<<<(n4o + 255) / 256, 256>>>((const float4*)Wout, (uint2*)Woh, n4o);
    }

    // 1) QKV projection (fp16 tensor cores) -> fp16 Q/K/V in [B,H,L,HD]
    mm_f16<0><<<dim3(3 * DD / 128, MR / 128), 256, GEMM_SMEM>>>(
        (const __half*)Xh, (const __half*)Wqh, nullptr, DD, 3 * DD);

    // 2) Fused RoPE + tensor-core flash attention -> g_Oh fp16 [B,L,D]
    attn_tc<<<BB * NH * NBLK, 256, ATTN_SMEM>>>();

    // 3) Output projection (fp16 tensor cores) -> fp32 out
    mm_f16<1><<<dim3(DD / 128, MR / 128), 256, GEMM_SMEM>>>(
        (const __half*)Oh, (const __half*)Woh, out, DD, DD);
}